// round 2
// baseline (speedup 1.0000x reference)
#include <cuda_runtime.h>

#define N_NODES 50000
#define N_EDGES 800000
#define DD 128

// ---------------- scratch (device globals: no allocation allowed) ------------
__device__ float g_h  [N_NODES * DD];        // current hidden state
__device__ float g_hw [N_NODES * DD];        // h @ Wgcn^T + b
__device__ float g_agg[N_NODES * DD];        // GCN aggregation
__device__ float g_gi [N_NODES * 3 * DD];    // input gates
__device__ float g_gh [N_NODES * 3 * DD];    // hidden gates
__device__ float g_max[N_NODES * DD];        // running elementwise max of layer outputs
__device__ float g_h2 [N_NODES * 64];        // fc2 output
__device__ float g_dinv[N_NODES];
__device__ int   g_deg [N_NODES];
__device__ int   g_is64;                     // edge_index dtype flag (detected per launch)

// ---------------- edge-index dtype detection --------------------------------
// Reference writes jnp.int64, but JAX without x64 silently emits int32. Detect
// on-device: random pairs of in-range int32 reinterpreted as int64 are
// astronomically out of [0, N) (hi word is a second nonzero index), so 256
// in-range int64 reads <=> buffer really is int64.
__global__ void detect_k(const void* __restrict__ p) {
    if (threadIdx.x == 0 && blockIdx.x == 0) {
        const long long* q = (const long long*)p;
        int ok = 1;
        for (int i = 0; i < 256; i++) {
            long long v = q[i];
            if (v < 0 || v >= N_NODES) { ok = 0; break; }
        }
        g_is64 = ok;
    }
}

__device__ __forceinline__ int eidx(const void* __restrict__ p, int i) {
    if (g_is64) return (int)((const long long*)p)[i];
    return ((const int*)p)[i];
}

// ---------------- degree / normalization -------------------------------------
__global__ void deg_init_k() {
    int i = blockIdx.x * blockDim.x + threadIdx.x;
    if (i < N_NODES) g_deg[i] = 1;                     // self loop
}
__global__ void deg_count_k(const void* __restrict__ ei) {
    int e = blockIdx.x * blockDim.x + threadIdx.x;
    if (e < N_EDGES) atomicAdd(&g_deg[eidx(ei, e)], 1); // degree over row (source) array
}
__global__ void dinv_k() {
    int i = blockIdx.x * blockDim.x + threadIdx.x;
    if (i < N_NODES) g_dinv[i] = rsqrtf((float)g_deg[i]);
}

// ---------------- fc1 + leaky relu + gmax init --------------------------------
__global__ void fc1_k(const float* __restrict__ x, const float* __restrict__ w,
                      const float* __restrict__ b) {
    int idx = blockIdx.x * blockDim.x + threadIdx.x;
    if (idx >= N_NODES * DD) return;
    int n = idx >> 7, d = idx & 127;
    float v = fmaf(x[n*3+0], w[d*3+0],
              fmaf(x[n*3+1], w[d*3+1],
              fmaf(x[n*3+2], w[d*3+2], b[d])));
    g_h[idx]   = v > 0.f ? v : 0.01f * v;
    g_max[idx] = -3.4e38f;
}

// ---------------- generic SGEMM: C[M,Nout] = A[M,128] @ B[Nout,128]^T + bias --
// BM=BN=128, BK=8, 8x8 microtiles, 256 threads.
// A/C selected by compile-time-uniform mode to avoid passing scratch pointers:
//   mode 0: A=g_h   -> C=g_hw   (Nout=128)
//   mode 1: A=g_agg -> C=g_gi   (Nout=384)
//   mode 2: A=g_h   -> C=g_gh   (Nout=384)
//   mode 3: A=g_max -> C=g_h2   (Nout=64, leaky relu)
__global__ __launch_bounds__(256) void sgemm128_k(
    const float* __restrict__ B, const float* __restrict__ bias,
    int Nout, int mode)
{
    const float* A;
    float* C;
    int act = 0;
    switch (mode) {
        case 0: A = g_h;   C = g_hw; break;
        case 1: A = g_agg; C = g_gi; break;
        case 2: A = g_h;   C = g_gh; break;
        default: A = g_max; C = g_h2; act = 1; break;
    }

    __shared__ float As[8][128];
    __shared__ float Bs[8][128];

    int tid = threadIdx.x;
    int bm = blockIdx.x * 128;
    int bn = blockIdx.y * 128;
    int row = tid >> 1;            // 0..127  (load row)
    int kq  = (tid & 1) * 4;       // 0 or 4  (k quad)
    int tx  = tid & 15;            // micro-tile col group
    int ty  = tid >> 4;            // micro-tile row group

    float acc[8][8];
#pragma unroll
    for (int i = 0; i < 8; i++)
#pragma unroll
        for (int j = 0; j < 8; j++) acc[i][j] = 0.f;

    const float4* A4 = (const float4*)A;
    const float4* B4 = (const float4*)B;

    for (int k0 = 0; k0 < 128; k0 += 8) {
        float4 av = make_float4(0.f, 0.f, 0.f, 0.f);
        float4 bv = make_float4(0.f, 0.f, 0.f, 0.f);
        int gm = bm + row;
        int gn = bn + row;
        if (gm < N_NODES) av = A4[(gm * 128 + k0 + kq) >> 2];
        if (gn < Nout)    bv = B4[(gn * 128 + k0 + kq) >> 2];
        __syncthreads();
        As[kq+0][row] = av.x; As[kq+1][row] = av.y; As[kq+2][row] = av.z; As[kq+3][row] = av.w;
        Bs[kq+0][row] = bv.x; Bs[kq+1][row] = bv.y; Bs[kq+2][row] = bv.z; Bs[kq+3][row] = bv.w;
        __syncthreads();
#pragma unroll
        for (int k = 0; k < 8; k++) {
            float4 a0 = *(const float4*)&As[k][ty * 8];
            float4 a1 = *(const float4*)&As[k][ty * 8 + 4];
            float4 b0 = *(const float4*)&Bs[k][tx * 8];
            float4 b1 = *(const float4*)&Bs[k][tx * 8 + 4];
            float a[8] = {a0.x, a0.y, a0.z, a0.w, a1.x, a1.y, a1.z, a1.w};
            float b[8] = {b0.x, b0.y, b0.z, b0.w, b1.x, b1.y, b1.z, b1.w};
#pragma unroll
            for (int i = 0; i < 8; i++)
#pragma unroll
                for (int j = 0; j < 8; j++)
                    acc[i][j] = fmaf(a[i], b[j], acc[i][j]);
        }
    }

    // store (Nout is always a multiple of 8, so per-group guard suffices)
    int cn = bn + tx * 8;
    if (cn >= Nout) return;
    float bb[8];
#pragma unroll
    for (int j = 0; j < 8; j++) bb[j] = bias[cn + j];
#pragma unroll
    for (int i = 0; i < 8; i++) {
        int gm = bm + ty * 8 + i;
        if (gm >= N_NODES) continue;
        float out[8];
#pragma unroll
        for (int j = 0; j < 8; j++) {
            float v = acc[i][j] + bb[j];
            out[j] = (act && v < 0.f) ? 0.01f * v : v;
        }
        float4* cp = (float4*)&C[(long long)gm * Nout + cn];
        cp[0] = make_float4(out[0], out[1], out[2], out[3]);
        cp[1] = make_float4(out[4], out[5], out[6], out[7]);
    }
}

// ---------------- SpMM: init agg with self-loop contribution -----------------
__global__ void spmm_init_k() {
    int idx = blockIdx.x * blockDim.x + threadIdx.x;
    if (idx >= N_NODES * 32) return;
    int n = idx >> 5;
    float s = g_dinv[n]; s = s * s;
    float4 v = ((const float4*)g_hw)[idx];
    ((float4*)g_agg)[idx] = make_float4(v.x * s, v.y * s, v.z * s, v.w * s);
}

// ---------------- SpMM: one warp per edge, vec4 reduction atomics ------------
__global__ __launch_bounds__(256) void spmm_edge_k(const void* __restrict__ ei) {
    int e = (blockIdx.x << 3) + (threadIdx.x >> 5);
    if (e >= N_EDGES) return;
    int lane = threadIdx.x & 31;
    int r = eidx(ei, e);
    int c = eidx(ei, N_EDGES + e);
    float nrm = g_dinv[r] * g_dinv[c];
    float4 v = ((const float4*)g_hw)[r * 32 + lane];
    float4* dst = ((float4*)g_agg) + c * 32 + lane;
    asm volatile("red.global.add.v4.f32 [%0], {%1, %2, %3, %4};"
                 :: "l"(dst), "f"(v.x * nrm), "f"(v.y * nrm),
                    "f"(v.z * nrm), "f"(v.w * nrm)
                 : "memory");
}

// ---------------- GRU gates + state update + running max ---------------------
__global__ void gru_k() {
    int idx = blockIdx.x * blockDim.x + threadIdx.x;
    if (idx >= N_NODES * DD) return;
    int n = idx >> 7, d = idx & 127;
    const float* gi = g_gi + n * 384;
    const float* gh = g_gh + n * 384;
    float r  = 1.f / (1.f + expf(-(gi[d]       + gh[d])));
    float z  = 1.f / (1.f + expf(-(gi[d + 128] + gh[d + 128])));
    float nn = tanhf(gi[d + 256] + r * gh[d + 256]);
    float hold = g_h[idx];
    float hnew = (1.f - z) * nn + z * hold;
    g_h[idx]   = hnew;
    g_max[idx] = fmaxf(g_max[idx], hnew);
}

// ---------------- fc3: [N,64] -> [N] ------------------------------------------
__global__ void fc3_k(const float* __restrict__ w, const float* __restrict__ b,
                      float* __restrict__ out) {
    int n = blockIdx.x * 8 + (threadIdx.x >> 5);
    if (n >= N_NODES) return;
    int lane = threadIdx.x & 31;
    const float* h2 = g_h2 + n * 64;
    float s = fmaf(h2[lane], w[lane], h2[lane + 32] * w[lane + 32]);
#pragma unroll
    for (int off = 16; off; off >>= 1) s += __shfl_xor_sync(0xffffffffu, s, off);
    if (lane == 0) out[n] = s + b[0];
}

// ---------------- launch ------------------------------------------------------
extern "C" void kernel_launch(void* const* d_in, const int* in_sizes, int n_in,
                              void* d_out, int out_size) {
    const float* x       = (const float*)d_in[0];
    const void*  ei      = d_in[1];
    const float* fc1_w   = (const float*)d_in[2];
    const float* fc1_b   = (const float*)d_in[3];
    const float* gcn_w   = (const float*)d_in[4];
    const float* gcn_b   = (const float*)d_in[5];
    const float* gru_wih = (const float*)d_in[6];
    const float* gru_whh = (const float*)d_in[7];
    const float* gru_bih = (const float*)d_in[8];
    const float* gru_bhh = (const float*)d_in[9];
    const float* fc2_w   = (const float*)d_in[10];
    const float* fc2_b   = (const float*)d_in[11];
    const float* fc3_w   = (const float*)d_in[12];
    const float* fc3_b   = (const float*)d_in[13];
    float* out = (float*)d_out;

    detect_k<<<1, 32>>>(ei);
    deg_init_k <<<(N_NODES + 255) / 256, 256>>>();
    deg_count_k<<<(N_EDGES + 255) / 256, 256>>>(ei);
    dinv_k     <<<(N_NODES + 255) / 256, 256>>>();
    fc1_k      <<<(N_NODES * DD + 255) / 256, 256>>>(x, fc1_w, fc1_b);

    dim3 g1(391, 1), g3(391, 3);
    for (int i = 0; i < 5; i++) {
        sgemm128_k<<<g1, 256>>>(gcn_w + i * DD * DD, gcn_b + i * DD, 128, 0);
        spmm_init_k<<<(N_NODES * 32 + 255) / 256, 256>>>();
        spmm_edge_k<<<N_EDGES / 8, 256>>>(ei);
        sgemm128_k<<<g3, 256>>>(gru_wih + i * 3 * DD * DD, gru_bih + i * 3 * DD, 384, 1);
        sgemm128_k<<<g3, 256>>>(gru_whh + i * 3 * DD * DD, gru_bhh + i * 3 * DD, 384, 2);
        gru_k<<<(N_NODES * DD + 255) / 256, 256>>>();
    }
    sgemm128_k<<<g1, 256>>>(fc2_w, fc2_b, 64, 3);
    fc3_k<<<(N_NODES + 7) / 8, 256>>>(fc3_w, fc3_b, out);
}

// round 5
// speedup vs baseline: 1.6188x; 1.6188x over previous
#include <cuda_runtime.h>

#define N_NODES 50000
#define N_EDGES 800000
#define DD 128
#define PADK 136   // smem row stride (floats): bank-conflict-free fragment loads

// ---------------- scratch (device globals: no allocation allowed) ------------
__device__ float g_h  [N_NODES * DD];
__device__ float g_hw [N_NODES * DD];
__device__ float g_agg[N_NODES * DD];
__device__ float g_gi [N_NODES * 3 * DD];
__device__ float g_gh [N_NODES * 3 * DD];
__device__ float g_max[N_NODES * DD];
__device__ float g_h2 [N_NODES * 64];
__device__ float g_dinv[N_NODES];
__device__ int   g_deg [N_NODES];
__device__ int   g_is64;

// ---------------- edge-index dtype detection ---------------------------------
// Reference declares int64; JAX without x64 silently emits int32. Detect on
// device: 256 consecutive int64 reads all in [0,N) <=> buffer really is int64.
__global__ void detect_k(const void* __restrict__ p) {
    if (threadIdx.x == 0 && blockIdx.x == 0) {
        const long long* q = (const long long*)p;
        int ok = 1;
        for (int i = 0; i < 256; i++) {
            long long v = q[i];
            if (v < 0 || v >= N_NODES) { ok = 0; break; }
        }
        g_is64 = ok;
    }
}
__device__ __forceinline__ int eidx(const void* __restrict__ p, int i) {
    if (g_is64) return (int)((const long long*)p)[i];
    return ((const int*)p)[i];
}

// ---------------- degree / normalization -------------------------------------
__global__ void deg_init_k() {
    int i = blockIdx.x * blockDim.x + threadIdx.x;
    if (i < N_NODES) g_deg[i] = 1;
}
__global__ void deg_count_k(const void* __restrict__ ei) {
    int e = blockIdx.x * blockDim.x + threadIdx.x;
    if (e < N_EDGES) atomicAdd(&g_deg[eidx(ei, e)], 1);
}
__global__ void dinv_k() {
    int i = blockIdx.x * blockDim.x + threadIdx.x;
    if (i < N_NODES) g_dinv[i] = rsqrtf((float)g_deg[i]);
}

// ---------------- fc1 + leaky relu + gmax init --------------------------------
__global__ void fc1_k(const float* __restrict__ x, const float* __restrict__ w,
                      const float* __restrict__ b) {
    int idx = blockIdx.x * blockDim.x + threadIdx.x;
    if (idx >= N_NODES * DD) return;
    int n = idx >> 7, d = idx & 127;
    float v = fmaf(x[n*3+0], w[d*3+0],
              fmaf(x[n*3+1], w[d*3+1],
              fmaf(x[n*3+2], w[d*3+2], b[d])));
    g_h[idx]   = v > 0.f ? v : 0.01f * v;
    g_max[idx] = -3.4e38f;
}

// ---------------- TF32 tensor-core GEMM ---------------------------------------
// C[M,Nout] = A[M,128] @ B[Nout,128]^T + bias
//   mode 0: A=g_h   -> C=g_hw, plus fused agg init: g_agg = dinv[m]^2 * C   (Nout=128)
//   mode 1: A=g_agg -> C=g_gi                                               (Nout=384)
//   mode 2: A=g_h   -> C=g_gh                                               (Nout=384)
// Block tile 128x128, 256 threads = 8 warps (2 M x 4 N), warp tile 64x32,
// m16n8k8 tf32 mma, K chunked by 16.
__device__ __forceinline__ unsigned f2tf32(float x) {
    unsigned r;
    asm("cvt.rna.tf32.f32 %0, %1;" : "=r"(r) : "f"(x));
    return r;
}
__device__ __forceinline__ void mma_tf32(float* c, const unsigned* a, const unsigned* b) {
    asm volatile("mma.sync.aligned.m16n8k8.row.col.f32.tf32.tf32.f32 "
                 "{%0,%1,%2,%3}, {%4,%5,%6,%7}, {%8,%9}, {%0,%1,%2,%3};"
                 : "+f"(c[0]), "+f"(c[1]), "+f"(c[2]), "+f"(c[3])
                 : "r"(a[0]), "r"(a[1]), "r"(a[2]), "r"(a[3]),
                   "r"(b[0]), "r"(b[1]));
}

__global__ __launch_bounds__(256) void tf32_gemm_k(
    const float* __restrict__ B, const float* __restrict__ bias,
    int Nout, int mode)
{
    const float* A;
    float* C;
    switch (mode) {
        case 0:  A = g_h;   C = g_hw; break;
        case 1:  A = g_agg; C = g_gi; break;
        default: A = g_h;   C = g_gh; break;
    }

    __shared__ unsigned As[16 * PADK];
    __shared__ unsigned Bs[16 * PADK];

    int tid  = threadIdx.x;
    int bm   = blockIdx.x * 128;
    int bn   = blockIdx.y * 128;
    int lrow = tid >> 1;            // 0..127 load row
    int kh   = (tid & 1) * 8;       // k half within 16-chunk

    int warpId = tid >> 5;
    int lane   = tid & 31;
    int wm = (warpId >> 2) * 64;    // warp M origin in tile
    int wn = (warpId & 3) * 32;     // warp N origin in tile
    int g  = lane >> 2;             // group id 0..7
    int t  = lane & 3;              // thread-in-group 0..3

    float acc[4][4][4];
#pragma unroll
    for (int i = 0; i < 4; i++)
#pragma unroll
        for (int j = 0; j < 4; j++)
#pragma unroll
            for (int v = 0; v < 4; v++) acc[i][j][v] = 0.f;

    const float4* A4 = (const float4*)A;
    const float4* B4 = (const float4*)B;

    for (int c = 0; c < 8; c++) {
        int k0 = c * 16;
        float4 va0 = make_float4(0.f,0.f,0.f,0.f), va1 = va0, vb0 = va0, vb1 = va0;
        int gm = bm + lrow;
        int gn = bn + lrow;
        if (gm < N_NODES) {
            va0 = A4[(gm * 128 + k0 + kh) >> 2];
            va1 = A4[(gm * 128 + k0 + kh + 4) >> 2];
        }
        if (gn < Nout) {
            vb0 = B4[(gn * 128 + k0 + kh) >> 2];
            vb1 = B4[(gn * 128 + k0 + kh + 4) >> 2];
        }
        __syncthreads();
        As[(kh+0)*PADK + lrow] = f2tf32(va0.x);
        As[(kh+1)*PADK + lrow] = f2tf32(va0.y);
        As[(kh+2)*PADK + lrow] = f2tf32(va0.z);
        As[(kh+3)*PADK + lrow] = f2tf32(va0.w);
        As[(kh+4)*PADK + lrow] = f2tf32(va1.x);
        As[(kh+5)*PADK + lrow] = f2tf32(va1.y);
        As[(kh+6)*PADK + lrow] = f2tf32(va1.z);
        As[(kh+7)*PADK + lrow] = f2tf32(va1.w);
        Bs[(kh+0)*PADK + lrow] = f2tf32(vb0.x);
        Bs[(kh+1)*PADK + lrow] = f2tf32(vb0.y);
        Bs[(kh+2)*PADK + lrow] = f2tf32(vb0.z);
        Bs[(kh+3)*PADK + lrow] = f2tf32(vb0.w);
        Bs[(kh+4)*PADK + lrow] = f2tf32(vb1.x);
        Bs[(kh+5)*PADK + lrow] = f2tf32(vb1.y);
        Bs[(kh+6)*PADK + lrow] = f2tf32(vb1.z);
        Bs[(kh+7)*PADK + lrow] = f2tf32(vb1.w);
        __syncthreads();

#pragma unroll
        for (int ks = 0; ks < 16; ks += 8) {
            unsigned af[4][4];
#pragma unroll
            for (int i = 0; i < 4; i++) {
                int r = wm + i * 16 + g;
                af[i][0] = As[(ks + t)     * PADK + r];
                af[i][1] = As[(ks + t)     * PADK + r + 8];
                af[i][2] = As[(ks + t + 4) * PADK + r];
                af[i][3] = As[(ks + t + 4) * PADK + r + 8];
            }
            unsigned bf[4][2];
#pragma unroll
            for (int j = 0; j < 4; j++) {
                int cn = wn + j * 8 + g;
                bf[j][0] = Bs[(ks + t)     * PADK + cn];
                bf[j][1] = Bs[(ks + t + 4) * PADK + cn];
            }
#pragma unroll
            for (int i = 0; i < 4; i++)
#pragma unroll
                for (int j = 0; j < 4; j++)
                    mma_tf32(acc[i][j], af[i], bf[j]);
        }
    }

    // epilogue: c0:(g,2t) c1:(g,2t+1) c2:(g+8,2t) c3:(g+8,2t+1)
#pragma unroll
    for (int i = 0; i < 4; i++) {
        int row0 = bm + wm + i * 16 + g;
        int row1 = row0 + 8;
        float s0 = 0.f, s1 = 0.f;
        if (mode == 0) {
            if (row0 < N_NODES) { float d = g_dinv[row0]; s0 = d * d; }
            if (row1 < N_NODES) { float d = g_dinv[row1]; s1 = d * d; }
        }
#pragma unroll
        for (int j = 0; j < 4; j++) {
            int cn = bn + wn + j * 8 + 2 * t;
            float b0 = bias[cn], b1 = bias[cn + 1];
            if (row0 < N_NODES) {
                float v0 = acc[i][j][0] + b0;
                float v1 = acc[i][j][1] + b1;
                *(float2*)&C[row0 * Nout + cn] = make_float2(v0, v1);
                if (mode == 0)
                    *(float2*)&g_agg[row0 * 128 + cn] = make_float2(v0 * s0, v1 * s0);
            }
            if (row1 < N_NODES) {
                float v2 = acc[i][j][2] + b0;
                float v3 = acc[i][j][3] + b1;
                *(float2*)&C[row1 * Nout + cn] = make_float2(v2, v3);
                if (mode == 0)
                    *(float2*)&g_agg[row1 * 128 + cn] = make_float2(v2 * s1, v3 * s1);
            }
        }
    }
}

// ---------------- fp32 SIMT SGEMM for fc2 (exact output head) -----------------
__global__ __launch_bounds__(256) void fc2_gemm_k(
    const float* __restrict__ B, const float* __restrict__ bias)
{
    const float* A = g_max;
    float* C = g_h2;
    const int Nout = 64;

    __shared__ float As[8][128];
    __shared__ float Bs[8][128];

    int tid = threadIdx.x;
    int bm = blockIdx.x * 128;
    int row = tid >> 1;
    int kq  = (tid & 1) * 4;
    int tx  = tid & 15;
    int ty  = tid >> 4;

    float acc[8][8];
#pragma unroll
    for (int i = 0; i < 8; i++)
#pragma unroll
        for (int j = 0; j < 8; j++) acc[i][j] = 0.f;

    const float4* A4 = (const float4*)A;
    const float4* B4 = (const float4*)B;

    for (int k0 = 0; k0 < 128; k0 += 8) {
        float4 av = make_float4(0.f,0.f,0.f,0.f);
        float4 bv = av;
        int gm = bm + row;
        if (gm < N_NODES) av = A4[(gm * 128 + k0 + kq) >> 2];
        if (row < Nout)   bv = B4[(row * 128 + k0 + kq) >> 2];
        __syncthreads();
        As[kq+0][row] = av.x; As[kq+1][row] = av.y; As[kq+2][row] = av.z; As[kq+3][row] = av.w;
        Bs[kq+0][row] = bv.x; Bs[kq+1][row] = bv.y; Bs[kq+2][row] = bv.z; Bs[kq+3][row] = bv.w;
        __syncthreads();
#pragma unroll
        for (int k = 0; k < 8; k++) {
            float4 a0 = *(const float4*)&As[k][ty * 8];
            float4 a1 = *(const float4*)&As[k][ty * 8 + 4];
            float4 b0 = *(const float4*)&Bs[k][tx * 8];
            float4 b1 = *(const float4*)&Bs[k][tx * 8 + 4];
            float a[8] = {a0.x, a0.y, a0.z, a0.w, a1.x, a1.y, a1.z, a1.w};
            float b[8] = {b0.x, b0.y, b0.z, b0.w, b1.x, b1.y, b1.z, b1.w};
#pragma unroll
            for (int i = 0; i < 8; i++)
#pragma unroll
                for (int j = 0; j < 8; j++)
                    acc[i][j] = fmaf(a[i], b[j], acc[i][j]);
        }
    }

    int cn = tx * 8;
    if (cn >= Nout) return;
    float bb[8];
#pragma unroll
    for (int j = 0; j < 8; j++) bb[j] = bias[cn + j];
#pragma unroll
    for (int i = 0; i < 8; i++) {
        int gm = bm + ty * 8 + i;
        if (gm >= N_NODES) continue;
        float out[8];
#pragma unroll
        for (int j = 0; j < 8; j++) {
            float v = acc[i][j] + bb[j];
            out[j] = v < 0.f ? 0.01f * v : v;
        }
        float4* cp = (float4*)&C[gm * Nout + cn];
        cp[0] = make_float4(out[0], out[1], out[2], out[3]);
        cp[1] = make_float4(out[4], out[5], out[6], out[7]);
    }
}

// ---------------- SpMM: one warp per edge, vec4 reduction atomics -------------
__global__ __launch_bounds__(256) void spmm_edge_k(const void* __restrict__ ei) {
    int e = (blockIdx.x << 3) + (threadIdx.x >> 5);
    if (e >= N_EDGES) return;
    int lane = threadIdx.x & 31;
    int r = eidx(ei, e);
    int c = eidx(ei, N_EDGES + e);
    float nrm = g_dinv[r] * g_dinv[c];
    float4 v = ((const float4*)g_hw)[r * 32 + lane];
    float4* dst = ((float4*)g_agg) + c * 32 + lane;
    asm volatile("red.global.add.v4.f32 [%0], {%1, %2, %3, %4};"
                 :: "l"(dst), "f"(v.x * nrm), "f"(v.y * nrm),
                    "f"(v.z * nrm), "f"(v.w * nrm)
                 : "memory");
}

// ---------------- GRU gates + state update + running max ----------------------
__global__ void gru_k() {
    int idx = blockIdx.x * blockDim.x + threadIdx.x;
    if (idx >= N_NODES * DD) return;
    int n = idx >> 7, d = idx & 127;
    const float* gi = g_gi + n * 384;
    const float* gh = g_gh + n * 384;
    float r  = 1.f / (1.f + expf(-(gi[d]       + gh[d])));
    float z  = 1.f / (1.f + expf(-(gi[d + 128] + gh[d + 128])));
    float nn = tanhf(gi[d + 256] + r * gh[d + 256]);
    float hold = g_h[idx];
    float hnew = (1.f - z) * nn + z * hold;
    g_h[idx]   = hnew;
    g_max[idx] = fmaxf(g_max[idx], hnew);
}

// ---------------- fc3: [N,64] -> [N] ------------------------------------------
__global__ void fc3_k(const float* __restrict__ w, const float* __restrict__ b,
                      float* __restrict__ out) {
    int n = blockIdx.x * 8 + (threadIdx.x >> 5);
    if (n >= N_NODES) return;
    int lane = threadIdx.x & 31;
    const float* h2 = g_h2 + n * 64;
    float s = fmaf(h2[lane], w[lane], h2[lane + 32] * w[lane + 32]);
#pragma unroll
    for (int off = 16; off; off >>= 1) s += __shfl_xor_sync(0xffffffffu, s, off);
    if (lane == 0) out[n] = s + b[0];
}

// ---------------- launch ------------------------------------------------------
extern "C" void kernel_launch(void* const* d_in, const int* in_sizes, int n_in,
                              void* d_out, int out_size) {
    const float* x       = (const float*)d_in[0];
    const void*  ei      = d_in[1];
    const float* fc1_w   = (const float*)d_in[2];
    const float* fc1_b   = (const float*)d_in[3];
    const float* gcn_w   = (const float*)d_in[4];
    const float* gcn_b   = (const float*)d_in[5];
    const float* gru_wih = (const float*)d_in[6];
    const float* gru_whh = (const float*)d_in[7];
    const float* gru_bih = (const float*)d_in[8];
    const float* gru_bhh = (const float*)d_in[9];
    const float* fc2_w   = (const float*)d_in[10];
    const float* fc2_b   = (const float*)d_in[11];
    const float* fc3_w   = (const float*)d_in[12];
    const float* fc3_b   = (const float*)d_in[13];
    float* out = (float*)d_out;

    detect_k<<<1, 32>>>(ei);
    deg_init_k <<<(N_NODES + 255) / 256, 256>>>();
    deg_count_k<<<(N_EDGES + 255) / 256, 256>>>(ei);
    dinv_k     <<<(N_NODES + 255) / 256, 256>>>();
    fc1_k      <<<(N_NODES * DD + 255) / 256, 256>>>(x, fc1_w, fc1_b);

    dim3 g1(391, 1), g3(391, 3);
    for (int i = 0; i < 5; i++) {
        tf32_gemm_k<<<g1, 256>>>(gcn_w + i * DD * DD, gcn_b + i * DD, 128, 0);
        spmm_edge_k<<<N_EDGES / 8, 256>>>(ei);
        tf32_gemm_k<<<g3, 256>>>(gru_wih + i * 3 * DD * DD, gru_bih + i * 3 * DD, 384, 1);
        tf32_gemm_k<<<g3, 256>>>(gru_whh + i * 3 * DD * DD, gru_bhh + i * 3 * DD, 384, 2);
        gru_k<<<(N_NODES * DD + 255) / 256, 256>>>();
    }
    fc2_gemm_k<<<g1, 256>>>(fc2_w, fc2_b);
    fc3_k<<<(N_NODES + 7) / 8, 256>>>(fc3_w, fc3_b, out);
}

// round 6
// speedup vs baseline: 1.9883x; 1.2283x over previous
#include <cuda_runtime.h>

#define N_NODES 50000
#define N_EDGES 800000
#define DD 128
#define PADK 136   // smem row stride (floats): bank-conflict-free fragment loads

// ---------------- scratch (device globals: no allocation allowed) ------------
__device__ float g_h  [N_NODES * DD];
__device__ float g_hw [N_NODES * DD];
__device__ float g_agg[N_NODES * DD];
__device__ float g_gi [N_NODES * 3 * DD];
__device__ float g_gh [N_NODES * 3 * DD];
__device__ float g_max[N_NODES * DD];
__device__ float g_h2 [N_NODES * 64];
__device__ float g_dinv[N_NODES];
__device__ int   g_deg  [N_NODES];     // out-(row-)degree + self loop, for dinv
__device__ int   g_indeg[N_NODES];     // in-(col-)degree, for CSC buckets
__device__ int   g_off  [N_NODES];     // CSC exclusive offsets
__device__ int   g_cur  [N_NODES];     // CSC fill cursors
__device__ int   g_bsum [64];          // scan block sums
__device__ int2  g_csc  [N_EDGES];     // {src, norm bits}
__device__ int   g_is64;

// ---------------- edge-index dtype detection ---------------------------------
__global__ void detect_k(const void* __restrict__ p) {
    if (threadIdx.x == 0 && blockIdx.x == 0) {
        const long long* q = (const long long*)p;
        int ok = 1;
        for (int i = 0; i < 256; i++) {
            long long v = q[i];
            if (v < 0 || v >= N_NODES) { ok = 0; break; }
        }
        g_is64 = ok;
    }
}
__device__ __forceinline__ int eidx(const void* __restrict__ p, int i) {
    if (g_is64) return (int)((const long long*)p)[i];
    return ((const int*)p)[i];
}

// ---------------- degree histograms ------------------------------------------
__global__ void deg_init_k() {
    int i = blockIdx.x * blockDim.x + threadIdx.x;
    if (i < N_NODES) { g_deg[i] = 1; g_indeg[i] = 0; g_cur[i] = 0; }
}
__global__ void hist_k(const void* __restrict__ ei) {
    int e = blockIdx.x * blockDim.x + threadIdx.x;
    if (e >= N_EDGES) return;
    atomicAdd(&g_deg[eidx(ei, e)], 1);              // row degree (normalization)
    atomicAdd(&g_indeg[eidx(ei, N_EDGES + e)], 1);  // col degree (CSC buckets)
}
__global__ void dinv_k() {
    int i = blockIdx.x * blockDim.x + threadIdx.x;
    if (i < N_NODES) g_dinv[i] = rsqrtf((float)g_deg[i]);
}

// ---------------- exclusive scan of g_indeg -> g_off (3 kernels) --------------
__global__ __launch_bounds__(1024) void scan1_k() {
    __shared__ int s[1024];
    int t = threadIdx.x;
    int i = blockIdx.x * 1024 + t;
    int v = (i < N_NODES) ? g_indeg[i] : 0;
    s[t] = v;
    __syncthreads();
#pragma unroll
    for (int d = 1; d < 1024; d <<= 1) {
        int x = (t >= d) ? s[t - d] : 0;
        __syncthreads();
        s[t] += x;
        __syncthreads();
    }
    if (i < N_NODES) g_off[i] = s[t];            // inclusive for now
    if (t == 1023) g_bsum[blockIdx.x] = s[1023];
}
__global__ void scan2_k(int nblk) {
    if (threadIdx.x == 0 && blockIdx.x == 0) {
        int acc = 0;
        for (int b = 0; b < nblk; b++) { int v = g_bsum[b]; g_bsum[b] = acc; acc += v; }
    }
}
__global__ void scan3_k() {
    int i = blockIdx.x * blockDim.x + threadIdx.x;
    if (i < N_NODES)
        g_off[i] = g_off[i] - g_indeg[i] + g_bsum[i >> 10];  // -> exclusive
}

// ---------------- CSC fill: {src, dinv[r]*dinv[c]} per in-edge ---------------
__global__ void fill_k(const void* __restrict__ ei) {
    int e = blockIdx.x * blockDim.x + threadIdx.x;
    if (e >= N_EDGES) return;
    int r = eidx(ei, e);
    int c = eidx(ei, N_EDGES + e);
    int p = g_off[c] + atomicAdd(&g_cur[c], 1);
    g_csc[p] = make_int2(r, __float_as_int(g_dinv[r] * g_dinv[c]));
}

// ---------------- fc1 + leaky relu + gmax init --------------------------------
__global__ void fc1_k(const float* __restrict__ x, const float* __restrict__ w,
                      const float* __restrict__ b) {
    int idx = blockIdx.x * blockDim.x + threadIdx.x;
    if (idx >= N_NODES * DD) return;
    int n = idx >> 7, d = idx & 127;
    float v = fmaf(x[n*3+0], w[d*3+0],
              fmaf(x[n*3+1], w[d*3+1],
              fmaf(x[n*3+2], w[d*3+2], b[d])));
    g_h[idx]   = v > 0.f ? v : 0.01f * v;
    g_max[idx] = -3.4e38f;
}

// ---------------- TF32 tensor-core GEMM (prefetch-pipelined) ------------------
// C[M,Nout] = A[M,128] @ B[Nout,128]^T + bias
//   mode 0: A=g_h   -> C=g_hw   (Nout=128)
//   mode 1: A=g_agg -> C=g_gi   (Nout=384)
//   mode 2: A=g_h   -> C=g_gh   (Nout=384)
__device__ __forceinline__ unsigned f2tf32(float x) {
    unsigned r;
    asm("cvt.rna.tf32.f32 %0, %1;" : "=r"(r) : "f"(x));
    return r;
}
__device__ __forceinline__ void mma_tf32(float* c, const unsigned* a, const unsigned* b) {
    asm volatile("mma.sync.aligned.m16n8k8.row.col.f32.tf32.tf32.f32 "
                 "{%0,%1,%2,%3}, {%4,%5,%6,%7}, {%8,%9}, {%0,%1,%2,%3};"
                 : "+f"(c[0]), "+f"(c[1]), "+f"(c[2]), "+f"(c[3])
                 : "r"(a[0]), "r"(a[1]), "r"(a[2]), "r"(a[3]),
                   "r"(b[0]), "r"(b[1]));
}

__global__ __launch_bounds__(256) void tf32_gemm_k(
    const float* __restrict__ B, const float* __restrict__ bias,
    int Nout, int mode)
{
    const float* A;
    float* C;
    switch (mode) {
        case 0:  A = g_h;   C = g_hw; break;
        case 1:  A = g_agg; C = g_gi; break;
        default: A = g_h;   C = g_gh; break;
    }

    __shared__ unsigned As[16 * PADK];
    __shared__ unsigned Bs[16 * PADK];

    int tid  = threadIdx.x;
    int bm   = blockIdx.x * 128;
    int bn   = blockIdx.y * 128;
    int lrow = tid >> 1;
    int kh   = (tid & 1) * 8;

    int warpId = tid >> 5;
    int lane   = tid & 31;
    int wm = (warpId >> 2) * 64;
    int wn = (warpId & 3) * 32;
    int g  = lane >> 2;
    int t  = lane & 3;

    float acc[4][4][4];
#pragma unroll
    for (int i = 0; i < 4; i++)
#pragma unroll
        for (int j = 0; j < 4; j++)
#pragma unroll
            for (int v = 0; v < 4; v++) acc[i][j][v] = 0.f;

    const float4* A4 = (const float4*)A;
    const float4* B4 = (const float4*)B;
    int gm = bm + lrow;
    int gn = bn + lrow;
    bool aok = gm < N_NODES;
    bool bok = gn < Nout;

    float4 va0, va1, vb0, vb1;
    const float4 z4 = make_float4(0.f, 0.f, 0.f, 0.f);

#define LOAD_CHUNK(K0)                                            \
    do {                                                          \
        va0 = va1 = vb0 = vb1 = z4;                               \
        if (aok) {                                                \
            va0 = A4[(gm * 128 + (K0) + kh) >> 2];                \
            va1 = A4[(gm * 128 + (K0) + kh + 4) >> 2];            \
        }                                                         \
        if (bok) {                                                \
            vb0 = B4[(gn * 128 + (K0) + kh) >> 2];                \
            vb1 = B4[(gn * 128 + (K0) + kh + 4) >> 2];            \
        }                                                         \
    } while (0)

    LOAD_CHUNK(0);

    for (int c = 0; c < 8; c++) {
        __syncthreads();   // prior compute done reading smem
        As[(kh+0)*PADK + lrow] = f2tf32(va0.x);
        As[(kh+1)*PADK + lrow] = f2tf32(va0.y);
        As[(kh+2)*PADK + lrow] = f2tf32(va0.z);
        As[(kh+3)*PADK + lrow] = f2tf32(va0.w);
        As[(kh+4)*PADK + lrow] = f2tf32(va1.x);
        As[(kh+5)*PADK + lrow] = f2tf32(va1.y);
        As[(kh+6)*PADK + lrow] = f2tf32(va1.z);
        As[(kh+7)*PADK + lrow] = f2tf32(va1.w);
        Bs[(kh+0)*PADK + lrow] = f2tf32(vb0.x);
        Bs[(kh+1)*PADK + lrow] = f2tf32(vb0.y);
        Bs[(kh+2)*PADK + lrow] = f2tf32(vb0.z);
        Bs[(kh+3)*PADK + lrow] = f2tf32(vb0.w);
        Bs[(kh+4)*PADK + lrow] = f2tf32(vb1.x);
        Bs[(kh+5)*PADK + lrow] = f2tf32(vb1.y);
        Bs[(kh+6)*PADK + lrow] = f2tf32(vb1.z);
        Bs[(kh+7)*PADK + lrow] = f2tf32(vb1.w);
        __syncthreads();

        if (c < 7) LOAD_CHUNK((c + 1) * 16);   // prefetch overlaps compute below

#pragma unroll
        for (int ks = 0; ks < 16; ks += 8) {
            unsigned af[4][4];
#pragma unroll
            for (int i = 0; i < 4; i++) {
                int r = wm + i * 16 + g;
                af[i][0] = As[(ks + t)     * PADK + r];
                af[i][1] = As[(ks + t)     * PADK + r + 8];
                af[i][2] = As[(ks + t + 4) * PADK + r];
                af[i][3] = As[(ks + t + 4) * PADK + r + 8];
            }
            unsigned bf[4][2];
#pragma unroll
            for (int j = 0; j < 4; j++) {
                int cn = wn + j * 8 + g;
                bf[j][0] = Bs[(ks + t)     * PADK + cn];
                bf[j][1] = Bs[(ks + t + 4) * PADK + cn];
            }
#pragma unroll
            for (int i = 0; i < 4; i++)
#pragma unroll
                for (int j = 0; j < 4; j++)
                    mma_tf32(acc[i][j], af[i], bf[j]);
        }
    }
#undef LOAD_CHUNK

    // epilogue: c0:(g,2t) c1:(g,2t+1) c2:(g+8,2t) c3:(g+8,2t+1)
#pragma unroll
    for (int i = 0; i < 4; i++) {
        int row0 = bm + wm + i * 16 + g;
        int row1 = row0 + 8;
#pragma unroll
        for (int j = 0; j < 4; j++) {
            int cn = bn + wn + j * 8 + 2 * t;
            float b0 = bias[cn], b1 = bias[cn + 1];
            if (row0 < N_NODES)
                *(float2*)&C[row0 * Nout + cn] =
                    make_float2(acc[i][j][0] + b0, acc[i][j][1] + b1);
            if (row1 < N_NODES)
                *(float2*)&C[row1 * Nout + cn] =
                    make_float2(acc[i][j][2] + b0, acc[i][j][3] + b1);
        }
    }
}

// ---------------- fp32 SIMT SGEMM for fc2 (exact output head) -----------------
__global__ __launch_bounds__(256) void fc2_gemm_k(
    const float* __restrict__ B, const float* __restrict__ bias)
{
    const float* A = g_max;
    float* C = g_h2;
    const int Nout = 64;

    __shared__ float As[8][128];
    __shared__ float Bs[8][128];

    int tid = threadIdx.x;
    int bm = blockIdx.x * 128;
    int row = tid >> 1;
    int kq  = (tid & 1) * 4;
    int tx  = tid & 15;
    int ty  = tid >> 4;

    float acc[8][8];
#pragma unroll
    for (int i = 0; i < 8; i++)
#pragma unroll
        for (int j = 0; j < 8; j++) acc[i][j] = 0.f;

    const float4* A4 = (const float4*)A;
    const float4* B4 = (const float4*)B;

    for (int k0 = 0; k0 < 128; k0 += 8) {
        float4 av = make_float4(0.f,0.f,0.f,0.f);
        float4 bv = av;
        int gm = bm + row;
        if (gm < N_NODES) av = A4[(gm * 128 + k0 + kq) >> 2];
        if (row < Nout)   bv = B4[(row * 128 + k0 + kq) >> 2];
        __syncthreads();
        As[kq+0][row] = av.x; As[kq+1][row] = av.y; As[kq+2][row] = av.z; As[kq+3][row] = av.w;
        Bs[kq+0][row] = bv.x; Bs[kq+1][row] = bv.y; Bs[kq+2][row] = bv.z; Bs[kq+3][row] = bv.w;
        __syncthreads();
#pragma unroll
        for (int k = 0; k < 8; k++) {
            float4 a0 = *(const float4*)&As[k][ty * 8];
            float4 a1 = *(const float4*)&As[k][ty * 8 + 4];
            float4 b0 = *(const float4*)&Bs[k][tx * 8];
            float4 b1 = *(const float4*)&Bs[k][tx * 8 + 4];
            float a[8] = {a0.x, a0.y, a0.z, a0.w, a1.x, a1.y, a1.z, a1.w};
            float b[8] = {b0.x, b0.y, b0.z, b0.w, b1.x, b1.y, b1.z, b1.w};
#pragma unroll
            for (int i = 0; i < 8; i++)
#pragma unroll
                for (int j = 0; j < 8; j++)
                    acc[i][j] = fmaf(a[i], b[j], acc[i][j]);
        }
    }

    int cn = tx * 8;
    if (cn >= Nout) return;
    float bb[8];
#pragma unroll
    for (int j = 0; j < 8; j++) bb[j] = bias[cn + j];
#pragma unroll
    for (int i = 0; i < 8; i++) {
        int gm = bm + ty * 8 + i;
        if (gm >= N_NODES) continue;
        float out[8];
#pragma unroll
        for (int j = 0; j < 8; j++) {
            float v = acc[i][j] + bb[j];
            out[j] = v < 0.f ? 0.01f * v : v;
        }
        float4* cp = (float4*)&C[gm * Nout + cn];
        cp[0] = make_float4(out[0], out[1], out[2], out[3]);
        cp[1] = make_float4(out[4], out[5], out[6], out[7]);
    }
}

// ---------------- SpMM gather: one warp per destination, no atomics ----------
__global__ __launch_bounds__(256) void spmm_gather_k() {
    int n = blockIdx.x * 8 + (threadIdx.x >> 5);
    if (n >= N_NODES) return;
    int lane = threadIdx.x & 31;
    const float4* hw4 = (const float4*)g_hw;

    float d = g_dinv[n];
    float s = d * d;
    float4 acc = hw4[n * 32 + lane];               // self-loop term
    acc.x *= s; acc.y *= s; acc.z *= s; acc.w *= s;

    int base = g_off[n];
    int cnt  = g_indeg[n];
    int k = 0;
    for (; k + 4 <= cnt; k += 4) {
        int2 p0 = g_csc[base + k];
        int2 p1 = g_csc[base + k + 1];
        int2 p2 = g_csc[base + k + 2];
        int2 p3 = g_csc[base + k + 3];
        float4 v0 = hw4[p0.x * 32 + lane];
        float4 v1 = hw4[p1.x * 32 + lane];
        float4 v2 = hw4[p2.x * 32 + lane];
        float4 v3 = hw4[p3.x * 32 + lane];
        float w0 = __int_as_float(p0.y), w1 = __int_as_float(p1.y);
        float w2 = __int_as_float(p2.y), w3 = __int_as_float(p3.y);
        acc.x = fmaf(w0, v0.x, acc.x); acc.y = fmaf(w0, v0.y, acc.y);
        acc.z = fmaf(w0, v0.z, acc.z); acc.w = fmaf(w0, v0.w, acc.w);
        acc.x = fmaf(w1, v1.x, acc.x); acc.y = fmaf(w1, v1.y, acc.y);
        acc.z = fmaf(w1, v1.z, acc.z); acc.w = fmaf(w1, v1.w, acc.w);
        acc.x = fmaf(w2, v2.x, acc.x); acc.y = fmaf(w2, v2.y, acc.y);
        acc.z = fmaf(w2, v2.z, acc.z); acc.w = fmaf(w2, v2.w, acc.w);
        acc.x = fmaf(w3, v3.x, acc.x); acc.y = fmaf(w3, v3.y, acc.y);
        acc.z = fmaf(w3, v3.z, acc.z); acc.w = fmaf(w3, v3.w, acc.w);
    }
    for (; k < cnt; k++) {
        int2 p = g_csc[base + k];
        float w = __int_as_float(p.y);
        float4 v = hw4[p.x * 32 + lane];
        acc.x = fmaf(w, v.x, acc.x); acc.y = fmaf(w, v.y, acc.y);
        acc.z = fmaf(w, v.z, acc.z); acc.w = fmaf(w, v.w, acc.w);
    }
    ((float4*)g_agg)[n * 32 + lane] = acc;
}

// ---------------- GRU gates + state update + running max ----------------------
__global__ void gru_k() {
    int idx = blockIdx.x * blockDim.x + threadIdx.x;
    if (idx >= N_NODES * DD) return;
    int n = idx >> 7, d = idx & 127;
    const float* gi = g_gi + n * 384;
    const float* gh = g_gh + n * 384;
    float r  = 1.f / (1.f + expf(-(gi[d]       + gh[d])));
    float z  = 1.f / (1.f + expf(-(gi[d + 128] + gh[d + 128])));
    float nn = tanhf(gi[d + 256] + r * gh[d + 256]);
    float hold = g_h[idx];
    float hnew = (1.f - z) * nn + z * hold;
    g_h[idx]   = hnew;
    g_max[idx] = fmaxf(g_max[idx], hnew);
}

// ---------------- fc3: [N,64] -> [N] ------------------------------------------
__global__ void fc3_k(const float* __restrict__ w, const float* __restrict__ b,
                      float* __restrict__ out) {
    int n = blockIdx.x * 8 + (threadIdx.x >> 5);
    if (n >= N_NODES) return;
    int lane = threadIdx.x & 31;
    const float* h2 = g_h2 + n * 64;
    float s = fmaf(h2[lane], w[lane], h2[lane + 32] * w[lane + 32]);
#pragma unroll
    for (int off = 16; off; off >>= 1) s += __shfl_xor_sync(0xffffffffu, s, off);
    if (lane == 0) out[n] = s + b[0];
}

// ---------------- launch ------------------------------------------------------
extern "C" void kernel_launch(void* const* d_in, const int* in_sizes, int n_in,
                              void* d_out, int out_size) {
    const float* x       = (const float*)d_in[0];
    const void*  ei      = d_in[1];
    const float* fc1_w   = (const float*)d_in[2];
    const float* fc1_b   = (const float*)d_in[3];
    const float* gcn_w   = (const float*)d_in[4];
    const float* gcn_b   = (const float*)d_in[5];
    const float* gru_wih = (const float*)d_in[6];
    const float* gru_whh = (const float*)d_in[7];
    const float* gru_bih = (const float*)d_in[8];
    const float* gru_bhh = (const float*)d_in[9];
    const float* fc2_w   = (const float*)d_in[10];
    const float* fc2_b   = (const float*)d_in[11];
    const float* fc3_w   = (const float*)d_in[12];
    const float* fc3_b   = (const float*)d_in[13];
    float* out = (float*)d_out;

    const int scan_blocks = (N_NODES + 1023) / 1024;   // 49

    detect_k<<<1, 32>>>(ei);
    deg_init_k<<<(N_NODES + 255) / 256, 256>>>();
    hist_k    <<<(N_EDGES + 255) / 256, 256>>>(ei);
    dinv_k    <<<(N_NODES + 255) / 256, 256>>>();
    scan1_k   <<<scan_blocks, 1024>>>();
    scan2_k   <<<1, 32>>>(scan_blocks);
    scan3_k   <<<(N_NODES + 255) / 256, 256>>>();
    fill_k    <<<(N_EDGES + 255) / 256, 256>>>(ei);
    fc1_k     <<<(N_NODES * DD + 255) / 256, 256>>>(x, fc1_w, fc1_b);

    dim3 g1(391, 1), g3(391, 3);
    for (int i = 0; i < 5; i++) {
        tf32_gemm_k<<<g1, 256>>>(gcn_w + i * DD * DD, gcn_b + i * DD, 128, 0);
        spmm_gather_k<<<(N_NODES + 7) / 8, 256>>>();
        tf32_gemm_k<<<g3, 256>>>(gru_wih + i * 3 * DD * DD, gru_bih + i * 3 * DD, 384, 1);
        tf32_gemm_k<<<g3, 256>>>(gru_whh + i * 3 * DD * DD, gru_bhh + i * 3 * DD, 384, 2);
        gru_k<<<(N_NODES * DD + 255) / 256, 256>>>();
    }
    fc2_gemm_k<<<g1, 256>>>(fc2_w, fc2_b);
    fc3_k<<<(N_NODES + 7) / 8, 256>>>(fc3_w, fc3_b, out);
}